// round 2
// baseline (speedup 1.0000x reference)
#include <cuda_runtime.h>

#define N_NODES 20000
#define N_EDGES 320000
#define E_TOT   (N_EDGES + N_NODES)
#define N_GRAPHS 64

// ---------------- scratch (device globals; no allocation allowed) ----------
__device__ float g_als1[N_NODES * 8];
__device__ float g_ald1[N_NODES * 8];
__device__ float g_o1[N_NODES * 64];
__device__ float g_t2[N_NODES * 64];
__device__ float g_als2[N_NODES];
__device__ float g_ald2[N_NODES];
__device__ float g_va[64];
__device__ float g_vd[64];
__device__ float g_Ps[24];
__device__ float g_Pd[24];
__device__ int   g_deg[N_NODES];
__device__ int   g_fill[N_NODES];
__device__ int   g_rowstart[N_NODES + 1];
__device__ int   g_csr[E_TOT];
__device__ float g_pool[N_GRAPHS * 512];
__device__ int   g_cnt[N_GRAPHS];

// ---------------- init: zero the accumulators --------------------------------
__global__ void k_init() {
    int i = blockIdx.x * blockDim.x + threadIdx.x;
    if (i < N_NODES) { g_deg[i] = 0; g_fill[i] = 0; }
    if (i < N_GRAPHS * 512) g_pool[i] = 0.f;
    if (i < N_GRAPHS) g_cnt[i] = 0;
}

// ---------------- CSR build (by dst), incl. self loops -----------------------
__global__ void k_hist(const int* __restrict__ ei) {
    int e = blockIdx.x * blockDim.x + threadIdx.x;
    if (e >= E_TOT) return;
    int dst = (e < N_EDGES) ? ei[N_EDGES + e] : (e - N_EDGES);
    atomicAdd(&g_deg[dst], 1);
}

__global__ void k_scan() {  // 1 block, 1024 threads
    __shared__ int part[1024];
    int tid = threadIdx.x;
    const int CH = 20;  // 1024*20 >= 20000
    int base = tid * CH;
    int s = 0;
    for (int i = 0; i < CH; i++) {
        int idx = base + i;
        if (idx < N_NODES) s += g_deg[idx];
    }
    part[tid] = s;
    __syncthreads();
    for (int off = 1; off < 1024; off <<= 1) {
        int v = (tid >= off) ? part[tid - off] : 0;
        __syncthreads();
        part[tid] += v;
        __syncthreads();
    }
    int run = (tid == 0) ? 0 : part[tid - 1];
    for (int i = 0; i < CH; i++) {
        int idx = base + i;
        if (idx < N_NODES) { g_rowstart[idx] = run; run += g_deg[idx]; }
    }
    if (tid == 1023) g_rowstart[N_NODES] = part[1023];
}

__global__ void k_scatter(const int* __restrict__ ei) {
    int e = blockIdx.x * blockDim.x + threadIdx.x;
    if (e >= E_TOT) return;
    int src, dst;
    if (e < N_EDGES) { src = ei[e]; dst = ei[N_EDGES + e]; }
    else             { src = e - N_EDGES; dst = src; }
    int pos = g_rowstart[dst] + atomicAdd(&g_fill[dst], 1);
    g_csr[pos] = src;
}

// ---------------- tiny precomputes -------------------------------------------
// P_s[h][d] = sum_c W1[d, h*8+c] * a_src1[h,c]   (and same for dst)
__global__ void k_P(const float* __restrict__ W1, const float* __restrict__ as1,
                    const float* __restrict__ ad1) {
    int t = threadIdx.x;
    if (t < 24) {
        int h = t / 3, d = t % 3;
        float ps = 0.f, pd = 0.f;
        for (int c = 0; c < 8; c++) {
            float w = W1[d * 64 + h * 8 + c];
            ps += w * as1[h * 8 + c];
            pd += w * ad1[h * 8 + c];
        }
        g_Ps[t] = ps;
        g_Pd[t] = pd;
    }
}

// va[k] = sum_c W2[k,c]*a_src2[c]; vd likewise
__global__ void k_va(const float* __restrict__ W2, const float* __restrict__ as2,
                     const float* __restrict__ ad2) {
    int warp = (blockIdx.x * blockDim.x + threadIdx.x) >> 5;
    int lane = threadIdx.x & 31;
    if (warp >= 64) return;
    float s = 0.f, d = 0.f;
    for (int c = lane; c < 512; c += 32) {
        float w = W2[warp * 512 + c];
        s += w * as2[c];
        d += w * ad2[c];
    }
    for (int off = 16; off; off >>= 1) {
        s += __shfl_down_sync(0xffffffffu, s, off);
        d += __shfl_down_sync(0xffffffffu, d, off);
    }
    if (lane == 0) { g_va[warp] = s; g_vd[warp] = d; }
}

// al_s1[n,h] = x[n,:] . P_s[h,:]
__global__ void k_al1(const float* __restrict__ x) {
    int idx = blockIdx.x * blockDim.x + threadIdx.x;
    if (idx >= N_NODES * 8) return;
    int n = idx >> 3, h = idx & 7;
    float x0 = x[n * 3], x1 = x[n * 3 + 1], x2 = x[n * 3 + 2];
    g_als1[idx] = x0 * g_Ps[h * 3] + x1 * g_Ps[h * 3 + 1] + x2 * g_Ps[h * 3 + 2];
    g_ald1[idx] = x0 * g_Pd[h * 3] + x1 * g_Pd[h * 3 + 1] + x2 * g_Pd[h * 3 + 2];
}

// ---------------- layer-1 aggregate + o1 + fused al2 logits ------------------
// thread = (node, head). Aggregates w*x[src] (3 floats), then projects with W1.
__global__ void k_agg1(const float* __restrict__ x, const float* __restrict__ W1,
                       const float* __restrict__ b1) {
    int gidx = blockIdx.x * 256 + threadIdx.x;  // exactly N_NODES*8 threads
    int n = gidx >> 3, h = gidx & 7;
    int s0 = g_rowstart[n], s1 = g_rowstart[n + 1];
    float ald = g_ald1[gidx];
    float wsum = 0.f, xa0 = 0.f, xa1 = 0.f, xa2 = 0.f;
    for (int i = s0; i < s1; i++) {
        int src = g_csr[i];
        float e = g_als1[src * 8 + h] + ald;
        e = (e > 0.f) ? e : 0.2f * e;
        float w = __expf(e);
        wsum += w;
        xa0 += w * x[src * 3 + 0];
        xa1 += w * x[src * 3 + 1];
        xa2 += w * x[src * 3 + 2];
    }
    float inv = 1.f / wsum;
    xa0 *= inv; xa1 *= inv; xa2 *= inv;
    float ps2 = 0.f, pd2 = 0.f;
#pragma unroll
    for (int c = 0; c < 8; c++) {
        int col = h * 8 + c;
        float o = xa0 * W1[col] + xa1 * W1[64 + col] + xa2 * W1[128 + col] + b1[col];
        o = (o > 0.f) ? o : (__expf(o) - 1.f);  // elu
        g_o1[n * 64 + col] = o;
        ps2 += o * g_va[col];
        pd2 += o * g_vd[col];
    }
    // reduce over the 8 head-lanes of this node -> layer-2 logits
    for (int off = 4; off; off >>= 1) {
        ps2 += __shfl_down_sync(0xffffffffu, ps2, off);
        pd2 += __shfl_down_sync(0xffffffffu, pd2, off);
    }
    if (h == 0) { g_als2[n] = ps2; g_ald2[n] = pd2; }
}

// ---------------- layer-2 aggregate in o1-space (64 wide) --------------------
__global__ void k_agg2() {
    int n = blockIdx.x;
    int t = threadIdx.x;  // 64
    int s0 = g_rowstart[n], s1 = g_rowstart[n + 1];
    float ald = g_ald2[n];
    float wsum = 0.f, acc = 0.f;
    for (int i = s0; i < s1; i++) {
        int src = g_csr[i];
        float e = g_als2[src] + ald;
        e = (e > 0.f) ? e : 0.2f * e;
        float w = __expf(e);
        wsum += w;
        acc += w * g_o1[src * 64 + t];
    }
    g_t2[n * 64 + t] = acc / wsum;
}

// ---------------- t2 @ W2 + b2, elu, fused mean-pool accumulation ------------
// block = 512 threads, 8 nodes per block (2500 blocks, 20000 = 2500*8 exactly)
__global__ void k_gemm2(const float* __restrict__ W2, const float* __restrict__ b2,
                        const int* __restrict__ batch) {
    __shared__ __align__(16) float shT[64 * 8];  // [col][node]
    int n0 = blockIdx.x * 8;
    int tid = threadIdx.x;
    {
        int node = tid >> 6, col = tid & 63;
        shT[col * 8 + node] = g_t2[(n0 + node) * 64 + col];
    }
    __syncthreads();
    float acc[8] = {0.f, 0.f, 0.f, 0.f, 0.f, 0.f, 0.f, 0.f};
    int c = tid;
#pragma unroll 4
    for (int k = 0; k < 64; k++) {
        float w = W2[k * 512 + c];
        float4 a = *(const float4*)&shT[k * 8];
        float4 b = *(const float4*)&shT[k * 8 + 4];
        acc[0] += a.x * w; acc[1] += a.y * w; acc[2] += a.z * w; acc[3] += a.w * w;
        acc[4] += b.x * w; acc[5] += b.y * w; acc[6] += b.z * w; acc[7] += b.w * w;
    }
    float bb = b2[c];
    int bprev = batch[n0];
    float run = 0.f;
#pragma unroll
    for (int i = 0; i < 8; i++) {
        float o = acc[i] + bb;
        o = (o > 0.f) ? o : (__expf(o) - 1.f);  // elu
        int bg = batch[n0 + i];
        if (bg != bprev) {
            atomicAdd(&g_pool[bprev * 512 + c], run);
            run = 0.f;
            bprev = bg;
        }
        run += o;
    }
    atomicAdd(&g_pool[bprev * 512 + c], run);
}

// ---------------- per-graph node counts --------------------------------------
__global__ void k_cnt(const int* __restrict__ batch) {
    __shared__ int sh[N_GRAPHS];
    if (threadIdx.x < N_GRAPHS) sh[threadIdx.x] = 0;
    __syncthreads();
    int n = blockIdx.x * blockDim.x + threadIdx.x;
    if (n < N_NODES) atomicAdd(&sh[batch[n]], 1);
    __syncthreads();
    if (threadIdx.x < N_GRAPHS && sh[threadIdx.x])
        atomicAdd(&g_cnt[threadIdx.x], sh[threadIdx.x]);
}

// ---------------- pooled @ Wo + bo --------------------------------------------
__global__ void k_final(const float* __restrict__ Wo, const float* __restrict__ bo,
                        float* __restrict__ out) {
    __shared__ float sp[512];
    int g = blockIdx.x, c = threadIdx.x;
    float cnt = (float)g_cnt[g];
    float inv = 1.f / fmaxf(cnt, 1.f);
    sp[c] = g_pool[g * 512 + c] * inv;
    __syncthreads();
    float acc = bo[c];
#pragma unroll 8
    for (int k = 0; k < 512; k++) acc += sp[k] * Wo[k * 512 + c];
    out[g * 512 + c] = acc;
}

// ---------------- launch -------------------------------------------------------
extern "C" void kernel_launch(void* const* d_in, const int* in_sizes, int n_in,
                              void* d_out, int out_size) {
    const float* x     = (const float*)d_in[0];
    const int*   ei    = (const int*)d_in[1];     // int32! (JAX x64 disabled)
    const int*   batch = (const int*)d_in[2];     // int32!
    const float* W1    = (const float*)d_in[3];
    const float* as1   = (const float*)d_in[4];
    const float* ad1   = (const float*)d_in[5];
    const float* b1    = (const float*)d_in[6];
    const float* W2    = (const float*)d_in[7];
    const float* as2   = (const float*)d_in[8];
    const float* ad2   = (const float*)d_in[9];
    const float* b2    = (const float*)d_in[10];
    const float* Wo    = (const float*)d_in[11];
    const float* bo    = (const float*)d_in[12];
    float* out = (float*)d_out;

    k_init<<<(N_GRAPHS * 512 + 255) / 256, 256>>>();
    k_hist<<<(E_TOT + 255) / 256, 256>>>(ei);
    k_scan<<<1, 1024>>>();
    k_scatter<<<(E_TOT + 255) / 256, 256>>>(ei);
    k_P<<<1, 32>>>(W1, as1, ad1);
    k_va<<<8, 256>>>(W2, as2, ad2);
    k_al1<<<(N_NODES * 8 + 255) / 256, 256>>>(x);
    k_agg1<<<(N_NODES * 8) / 256, 256>>>(x, W1, b1);
    k_agg2<<<N_NODES, 64>>>();
    k_gemm2<<<N_NODES / 8, 512>>>(W2, b2, batch);
    k_cnt<<<(N_NODES + 255) / 256, 256>>>(batch);
    k_final<<<N_GRAPHS, 512>>>(Wo, bo, out);
}